// round 1
// baseline (speedup 1.0000x reference)
#include <cuda_runtime.h>
#include <math.h>

// ---------------------------------------------------------------------------
// Model_89197880803680: hierarchical TS transformer.
// Attention collapses algebraically (all L tokens identical -> softmax uniform
// -> o == v row). Per block:
//   x += (softplus(softplus(x Wl^T) Wl1^T)) M^T + c,  M = W20 Wo Wv,
//   c = W20 (Wo bv + bo)
// Final: out = x Wfc2^T.
// Wq/bq/Wk/bk/level_ids are dead.
// ---------------------------------------------------------------------------

#define NSER 19000
#define TT   168
#define UU   256
#define HORZ 24
#define NBLK 3

// scratch (device globals: allocation-free per harness rules)
__device__ float g_X [NSER * TT];
__device__ float g_H1[NSER * UU];
__device__ float g_H2[NSER * UU];
__device__ float g_tmp[NBLK * UU * UU];   // Wo @ Wv per block
__device__ float g_M  [NBLK * TT * UU];   // W20 @ Wo @ Wv
__device__ float g_bvo[NBLK * UU];        // Wo bv + bo
__device__ float g_c  [NBLK * TT];        // W20 (Wo bv + bo)

__device__ __forceinline__ float softplusf(float v) {
    return v > 20.f ? v : log1pf(__expf(v));
}

// ---------------------------------------------------------------------------
// Small batched NN GEMM for weight folding: C[b] = A[b] @ B[b]
// A row-major (Mr,K), B row-major (K,Nc). 16x16 tiles. Perf-irrelevant.
// ---------------------------------------------------------------------------
__global__ void gemm_nn_batched(const float* __restrict__ A, long sA,
                                const float* __restrict__ B, long sB,
                                float* __restrict__ C, long sC,
                                int Mr, int Nc, int K)
{
    __shared__ float As[16][16];
    __shared__ float Bs[16][17];
    int b = blockIdx.z;
    A += (long)b * sA; B += (long)b * sB; C += (long)b * sC;
    int row = blockIdx.y * 16 + threadIdx.y;
    int col = blockIdx.x * 16 + threadIdx.x;
    float acc = 0.f;
    for (int k0 = 0; k0 < K; k0 += 16) {
        As[threadIdx.y][threadIdx.x] =
            (row < Mr) ? A[(long)row * K + k0 + threadIdx.x] : 0.f;
        Bs[threadIdx.y][threadIdx.x] =
            (col < Nc) ? B[(long)(k0 + threadIdx.y) * Nc + col] : 0.f;
        __syncthreads();
#pragma unroll
        for (int k = 0; k < 16; k++)
            acc += As[threadIdx.y][k] * Bs[k][threadIdx.x];
        __syncthreads();
    }
    if (row < Mr && col < Nc) C[(long)row * Nc + col] = acc;
}

// ---------------------------------------------------------------------------
// Bias folding: bvo = Wo bv + bo ; c = W20 bvo. One block per hierarchy block.
// ---------------------------------------------------------------------------
__global__ void bias_fold(const float* __restrict__ Wo,
                          const float* __restrict__ bv,
                          const float* __restrict__ bo,
                          const float* __restrict__ W20)
{
    int b = blockIdx.x;
    int t = threadIdx.x;  // 0..255
    const float* Wo_b  = Wo  + (long)b * UU * UU;
    const float* bv_b  = bv  + (long)b * UU;
    const float* bo_b  = bo  + (long)b * UU;
    const float* W20_b = W20 + (long)b * TT * UU;

    __shared__ float sbvo[UU];
    float acc = bo_b[t];
    for (int k = 0; k < UU; k++) acc += Wo_b[t * UU + k] * bv_b[k];
    g_bvo[b * UU + t] = acc;
    sbvo[t] = acc;
    __syncthreads();
    if (t < TT) {
        float a = 0.f;
        for (int i = 0; i < UU; i++) a += W20_b[t * UU + i] * sbvo[i];
        g_c[b * TT + t] = a;
    }
}

// ---------------------------------------------------------------------------
// Main GEMM: C[m,n] = epilogue( sum_k A[m,k] * B[n,k] )   (B transposed form)
// BM=BN=128, BK=8, 256 threads, 8x8 microtile, register-prefetch pipeline.
// Requires K % 8 == 0 (168, 256 both OK). Row/col guards on M, Nc.
// EPI: 0 = softplus, 1 = resid + acc + cvec[n], 2 = plain
// ---------------------------------------------------------------------------
template <int EPI>
__global__ void __launch_bounds__(256, 2)
gemm_tn(const float* __restrict__ A, const float* __restrict__ B,
        float* __restrict__ C, const float* __restrict__ resid,
        const float* __restrict__ cvec,
        int Mr, int Nc, int K)
{
    __shared__ float As[8][128];
    __shared__ float Bs[8][128];

    const int tid  = threadIdx.x;
    const int lrow = tid >> 1;          // 0..127  (loader row within tile)
    const int lk   = (tid & 1) * 4;     // 0 or 4  (loader k offset)
    const int mrow = (tid >> 4) * 8;    // 0..120  compute rows
    const int ncol = (tid & 15) * 8;    // 0..120  compute cols

    const int mBase = blockIdx.y * 128;
    const int nBase = blockIdx.x * 128;

    const int ga = mBase + lrow;        // global A row this thread loads
    const int gb = nBase + lrow;        // global B row this thread loads

    float acc[8][8];
#pragma unroll
    for (int i = 0; i < 8; i++)
#pragma unroll
        for (int j = 0; j < 8; j++) acc[i][j] = 0.f;

    // prologue: load k0 = 0
    float4 av = make_float4(0.f, 0.f, 0.f, 0.f);
    float4 bvv = make_float4(0.f, 0.f, 0.f, 0.f);
    if (ga < Mr) av  = *(const float4*)(A + (long)ga * K + lk);
    if (gb < Nc) bvv = *(const float4*)(B + (long)gb * K + lk);

    for (int k0 = 0; k0 < K; k0 += 8) {
        __syncthreads();
        As[lk + 0][lrow] = av.x;  As[lk + 1][lrow] = av.y;
        As[lk + 2][lrow] = av.z;  As[lk + 3][lrow] = av.w;
        Bs[lk + 0][lrow] = bvv.x; Bs[lk + 1][lrow] = bvv.y;
        Bs[lk + 2][lrow] = bvv.z; Bs[lk + 3][lrow] = bvv.w;
        __syncthreads();

        // prefetch next k tile while computing this one
        if (k0 + 8 < K) {
            av  = make_float4(0.f, 0.f, 0.f, 0.f);
            bvv = make_float4(0.f, 0.f, 0.f, 0.f);
            if (ga < Mr) av  = *(const float4*)(A + (long)ga * K + k0 + 8 + lk);
            if (gb < Nc) bvv = *(const float4*)(B + (long)gb * K + k0 + 8 + lk);
        }

#pragma unroll
        for (int k = 0; k < 8; k++) {
            float4 a0 = *(const float4*)&As[k][mrow];
            float4 a1 = *(const float4*)&As[k][mrow + 4];
            float4 b0 = *(const float4*)&Bs[k][ncol];
            float4 b1 = *(const float4*)&Bs[k][ncol + 4];
            float ar[8] = {a0.x, a0.y, a0.z, a0.w, a1.x, a1.y, a1.z, a1.w};
            float br[8] = {b0.x, b0.y, b0.z, b0.w, b1.x, b1.y, b1.z, b1.w};
#pragma unroll
            for (int i = 0; i < 8; i++)
#pragma unroll
                for (int j = 0; j < 8; j++)
                    acc[i][j] = fmaf(ar[i], br[j], acc[i][j]);
        }
    }

    // epilogue
#pragma unroll
    for (int i = 0; i < 8; i++) {
        int r = mBase + mrow + i;
        if (r >= Mr) break;
#pragma unroll
        for (int j = 0; j < 8; j++) {
            int cc = nBase + ncol + j;
            if (cc >= Nc) continue;
            float v = acc[i][j];
            if (EPI == 0) {
                v = softplusf(v);
            } else if (EPI == 1) {
                v = resid[(long)r * Nc + cc] + v + cvec[cc];
            }
            C[(long)r * Nc + cc] = v;
        }
    }
}

// ---------------------------------------------------------------------------
extern "C" void kernel_launch(void* const* d_in, const int* in_sizes, int n_in,
                              void* d_out, int out_size)
{
    const float* x    = (const float*)d_in[0];   // (N, 168)
    const float* Wl   = (const float*)d_in[1];   // (3, 256, 168)
    const float* Wl1  = (const float*)d_in[2];   // (3, 256, 256)
    // d_in[3..6] = Wq, bq, Wk, bk : dead (attention degenerates)
    const float* Wv   = (const float*)d_in[7];   // (3, 256, 256)
    const float* bv   = (const float*)d_in[8];   // (3, 256)
    const float* Wo   = (const float*)d_in[9];   // (3, 256, 256)
    const float* bo   = (const float*)d_in[10];  // (3, 256)
    const float* W20  = (const float*)d_in[11];  // (3, 168, 256)
    const float* Wfc2 = (const float*)d_in[12];  // (24, 168)
    // d_in[13] = level_ids : dead
    float* out = (float*)d_out;

    const int N = in_sizes[0] / TT;              // 19000

    float *pX, *pH1, *pH2, *pTmp, *pM, *pC;
    cudaGetSymbolAddress((void**)&pX,   g_X);
    cudaGetSymbolAddress((void**)&pH1,  g_H1);
    cudaGetSymbolAddress((void**)&pH2,  g_H2);
    cudaGetSymbolAddress((void**)&pTmp, g_tmp);
    cudaGetSymbolAddress((void**)&pM,   g_M);
    cudaGetSymbolAddress((void**)&pC,   g_c);

    dim3 t16(16, 16);
    // tmp_b = Wo_b @ Wv_b  (256x256x256, batched over 3)
    gemm_nn_batched<<<dim3(16, 16, NBLK), t16>>>(
        Wo, (long)UU * UU, Wv, (long)UU * UU, pTmp, (long)UU * UU, UU, UU, UU);
    // M_b = W20_b @ tmp_b  (168x256x256)
    gemm_nn_batched<<<dim3(16, 11, NBLK), t16>>>(
        W20, (long)TT * UU, pTmp, (long)UU * UU, pM, (long)TT * UU, TT, UU, UU);
    // c_b = W20_b (Wo_b bv_b + bo_b)
    bias_fold<<<NBLK, UU>>>(Wo, bv, bo, W20);

    const int mt = (N + 127) / 128;              // 149 row tiles
    for (int b = 0; b < NBLK; b++) {
        const float* Ain   = (b == 0) ? x : pX;
        const float* Resid = (b == 0) ? x : pX;
        // H1 = softplus(A @ Wl_b^T)        (N x 256, K=168)
        gemm_tn<0><<<dim3(2, mt), 256>>>(
            Ain, Wl + (long)b * UU * TT, pH1, nullptr, nullptr, N, UU, TT);
        // H2 = softplus(H1 @ Wl1_b^T)      (N x 256, K=256)
        gemm_tn<0><<<dim3(2, mt), 256>>>(
            pH1, Wl1 + (long)b * UU * UU, pH2, nullptr, nullptr, N, UU, UU);
        // X = resid + H2 @ M_b^T + c_b     (N x 168, K=256)
        gemm_tn<1><<<dim3(2, mt), 256>>>(
            pH2, pM + (long)b * TT * UU, pX, Resid, pC + (long)b * TT, N, TT, UU);
    }
    // out = X @ Wfc2^T                     (N x 24, K=168)
    gemm_tn<2><<<dim3(1, mt), 256>>>(
        pX, Wfc2, out, nullptr, nullptr, N, HORZ, TT);
}

// round 3
// speedup vs baseline: 1.6109x; 1.6109x over previous
#include <cuda_runtime.h>
#include <cuda_bf16.h>
#include <math.h>

// ---------------------------------------------------------------------------
// Model_89197880803680.
// Attention collapses (all L tokens identical -> softmax uniform -> o == v).
// Per block:  x += softplus(softplus(x Wl^T) Wl1^T) M^T + c,
//   M = W20 Wo Wv,  c = W20 (Wo bv + bo).   Final: out = x Wfc2^T.
// GEMMs run on tensor cores: bf16 3-mma split (hi*hi + hi*lo + lo*hi, f32 acc).
// ---------------------------------------------------------------------------

#define NSER 19000
#define TT   168
#define UU   256
#define HORZ 24
#define NBLK 3
#define KP1  192          // padded K for 168

typedef unsigned int uint;

// fp32 scratch
__device__ float g_X  [NSER * TT];
__device__ float g_tmp[NBLK * UU * UU];
__device__ float g_M  [NBLK * TT * UU];
__device__ float g_c  [NBLK * TT];

// bf16 split buffers [0]=hi, [1]=lo
__device__ __nv_bfloat16 g_xs  [2][NSER * KP1];   // split of input x  (N,192)
__device__ __nv_bfloat16 g_Xs  [2][NSER * KP1];   // split of running X (N,192); pad cols stay 0
__device__ __nv_bfloat16 g_H1s [2][NSER * UU];
__device__ __nv_bfloat16 g_H2s [2][NSER * UU];
__device__ __nv_bfloat16 g_Wls [2][NBLK * UU * KP1];
__device__ __nv_bfloat16 g_Wl1s[2][NBLK * UU * UU];
__device__ __nv_bfloat16 g_Ms  [2][NBLK * UU * UU];  // M padded to 256 rows

__device__ __forceinline__ float softplusf(float v) {
    return v > 20.f ? v : log1pf(__expf(v));
}
__device__ __forceinline__ void split2(float v, __nv_bfloat16& h, __nv_bfloat16& l) {
    h = __float2bfloat16(v);
    l = __float2bfloat16(v - __bfloat162float(h));
}

// ---------------------------------------------------------------------------
// weight folding (tiny, fp32)
// ---------------------------------------------------------------------------
__global__ void gemm_nn_batched(const float* __restrict__ A, long sA,
                                const float* __restrict__ B, long sB,
                                float* __restrict__ C, long sC,
                                int Mr, int Nc, int K)
{
    __shared__ float As[16][16];
    __shared__ float Bs[16][17];
    int b = blockIdx.z;
    A += (long)b * sA; B += (long)b * sB; C += (long)b * sC;
    int row = blockIdx.y * 16 + threadIdx.y;
    int col = blockIdx.x * 16 + threadIdx.x;
    float acc = 0.f;
    for (int k0 = 0; k0 < K; k0 += 16) {
        As[threadIdx.y][threadIdx.x] = (row < Mr) ? A[(long)row * K + k0 + threadIdx.x] : 0.f;
        Bs[threadIdx.y][threadIdx.x] = (col < Nc) ? B[(long)(k0 + threadIdx.y) * Nc + col] : 0.f;
        __syncthreads();
#pragma unroll
        for (int k = 0; k < 16; k++) acc += As[threadIdx.y][k] * Bs[k][threadIdx.x];
        __syncthreads();
    }
    if (row < Mr && col < Nc) C[(long)row * Nc + col] = acc;
}

__global__ void bias_fold(const float* __restrict__ Wo, const float* __restrict__ bv,
                          const float* __restrict__ bo, const float* __restrict__ W20)
{
    int b = blockIdx.x, t = threadIdx.x;
    const float* Wo_b  = Wo  + (long)b * UU * UU;
    const float* W20_b = W20 + (long)b * TT * UU;
    __shared__ float sbvo[UU];
    float acc = bo[b * UU + t];
    for (int k = 0; k < UU; k++) acc += Wo_b[t * UU + k] * bv[b * UU + k];
    sbvo[t] = acc;
    __syncthreads();
    if (t < TT) {
        float a = 0.f;
        for (int i = 0; i < UU; i++) a += W20_b[t * UU + i] * sbvo[i];
        g_c[b * TT + t] = a;
    }
}

// ---------------------------------------------------------------------------
// split fp32 (rows_in, Kin) -> bf16 hi/lo (rows_out, Kout), zero-padded
// ---------------------------------------------------------------------------
__global__ void split_pad(const float* __restrict__ src, int rows_in, int Kin,
                          __nv_bfloat16* __restrict__ hi, __nv_bfloat16* __restrict__ lo,
                          long total, int Kout)
{
    long idx = (long)blockIdx.x * blockDim.x + threadIdx.x;
    if (idx >= total) return;
    int r = (int)(idx / Kout), c = (int)(idx % Kout);
    float v = (r < rows_in && c < Kin) ? src[(long)r * Kin + c] : 0.f;
    __nv_bfloat16 h, l;
    split2(v, h, l);
    hi[idx] = h; lo[idx] = l;
}

// ---------------------------------------------------------------------------
// Tensor-core GEMM: C(m,n) = sum_k A[m,k]*B[n,k],  A/B as bf16 hi+lo splits.
// BM=BN=128, BK=32, 256 threads, 8 warps (2x4), warp tile 64x32.
// cp.async double buffered. K % 32 == 0. B buffers have >= nBase+128 rows.
// EPI 0: H = softplus(acc)           -> split store (ld 256)
// EPI 1: v = resid + acc + cvec[n]   -> fp32 X (ld 168) + split store (ld 192)
// ---------------------------------------------------------------------------
#define TILE_B 10240                    // bytes per 128x40-bf16 tile
#define STAGE_B (4 * TILE_B)            // Ahi,Alo,Bhi,Blo
#define SMEM_DYN (2 * STAGE_B)          // 81920

__device__ __forceinline__ void cpa16(uint dst, const void* src, bool pred) {
    int sz = pred ? 16 : 0;
    asm volatile("cp.async.cg.shared.global [%0], [%1], 16, %2;\n"
                 :: "r"(dst), "l"(src), "r"(sz));
}
__device__ __forceinline__ void mma16816(float* c, const uint* a, const uint* b) {
    asm volatile("mma.sync.aligned.m16n8k16.row.col.f32.bf16.bf16.f32 "
                 "{%0,%1,%2,%3}, {%4,%5,%6,%7}, {%8,%9}, {%0,%1,%2,%3};"
                 : "+f"(c[0]), "+f"(c[1]), "+f"(c[2]), "+f"(c[3])
                 : "r"(a[0]), "r"(a[1]), "r"(a[2]), "r"(a[3]), "r"(b[0]), "r"(b[1]));
}

template <int EPI>
__global__ void __launch_bounds__(256)
mma_gemm(const __nv_bfloat16* __restrict__ Ahi, const __nv_bfloat16* __restrict__ Alo,
         const __nv_bfloat16* __restrict__ Bhi, const __nv_bfloat16* __restrict__ Blo,
         int Mr, int K, int NcValid,
         __nv_bfloat16* __restrict__ outHi, __nv_bfloat16* __restrict__ outLo, int ldS,
         float* __restrict__ outF, const float* __restrict__ resid,
         const float* __restrict__ cvec)
{
    extern __shared__ __nv_bfloat16 sm[];
    const int tid   = threadIdx.x;
    const int mBase = blockIdx.y * 128;
    const int nBase = blockIdx.x * 128;
    const uint smBase = (uint)__cvta_generic_to_shared(sm);

    const int warp = tid >> 5, lane = tid & 31;
    const int g = lane >> 2, t = lane & 3;
    const int wm = (warp >> 2) * 64;   // 0 / 64
    const int wn = (warp & 3) * 32;    // 0..96

    float acc[4][4][4];
#pragma unroll
    for (int i = 0; i < 4; i++)
#pragma unroll
        for (int j = 0; j < 4; j++)
#pragma unroll
            for (int r = 0; r < 4; r++) acc[i][j][r] = 0.f;

    const int nIter = K >> 5;

    // loader: 512 int4 per tile-kind, 2 per thread
    const int lrow0 = tid >> 2;            // 0..63
    const int lq    = tid & 3;             // 16B chunk within 64B row chunk

    auto issue_stage = [&](int it, int s) {
        const long k0 = (long)it << 5;
        uint base = smBase + s * STAGE_B;
#pragma unroll
        for (int p = 0; p < 2; p++) {
            int row = lrow0 + p * 64;
            uint soff = (uint)(row * 80 + lq * 16);
            long aoff = (long)(mBase + row) * K + k0 + lq * 8;
            bool pa = (mBase + row) < Mr;
            long aoffc = pa ? aoff : 0;
            cpa16(base + 0 * TILE_B + soff, Ahi + aoffc, pa);
            cpa16(base + 1 * TILE_B + soff, Alo + aoffc, pa);
            long boff = (long)(nBase + row) * K + k0 + lq * 8;
            cpa16(base + 2 * TILE_B + soff, Bhi + boff, true);
            cpa16(base + 3 * TILE_B + soff, Blo + boff, true);
        }
        asm volatile("cp.async.commit_group;");
    };

    issue_stage(0, 0);

    for (int it = 0; it < nIter; it++) {
        const int s = it & 1;
        if (it + 1 < nIter) {
            issue_stage(it + 1, s ^ 1);
            asm volatile("cp.async.wait_group 1;");
        } else {
            asm volatile("cp.async.wait_group 0;");
        }
        __syncthreads();

        const __nv_bfloat16* pAh = sm + (long)s * (STAGE_B / 2) + 0 * (TILE_B / 2);
        const __nv_bfloat16* pAl = pAh + (TILE_B / 2);
        const __nv_bfloat16* pBh = pAh + 2 * (TILE_B / 2);
        const __nv_bfloat16* pBl = pAh + 3 * (TILE_B / 2);

#pragma unroll
        for (int ks = 0; ks < 32; ks += 16) {
            const int kk = ks + 2 * t;
            uint bh[4][2], bl[4][2];
#pragma unroll
            for (int j = 0; j < 4; j++) {
                int col = wn + j * 8 + g;
                bh[j][0] = *(const uint*)(pBh + col * 40 + kk);
                bh[j][1] = *(const uint*)(pBh + col * 40 + kk + 8);
                bl[j][0] = *(const uint*)(pBl + col * 40 + kk);
                bl[j][1] = *(const uint*)(pBl + col * 40 + kk + 8);
            }
#pragma unroll
            for (int i = 0; i < 4; i++) {
                int ar = wm + i * 16 + g;
                uint ah[4], al[4];
                ah[0] = *(const uint*)(pAh + ar * 40 + kk);
                ah[1] = *(const uint*)(pAh + (ar + 8) * 40 + kk);
                ah[2] = *(const uint*)(pAh + ar * 40 + kk + 8);
                ah[3] = *(const uint*)(pAh + (ar + 8) * 40 + kk + 8);
                al[0] = *(const uint*)(pAl + ar * 40 + kk);
                al[1] = *(const uint*)(pAl + (ar + 8) * 40 + kk);
                al[2] = *(const uint*)(pAl + ar * 40 + kk + 8);
                al[3] = *(const uint*)(pAl + (ar + 8) * 40 + kk + 8);
#pragma unroll
                for (int j = 0; j < 4; j++) {
                    mma16816(acc[i][j], ah, bh[j]);
                    mma16816(acc[i][j], ah, bl[j]);
                    mma16816(acc[i][j], al, bh[j]);
                }
            }
        }
        __syncthreads();
    }

    // epilogue
#pragma unroll
    for (int i = 0; i < 4; i++) {
#pragma unroll
        for (int j = 0; j < 4; j++) {
            int c0 = nBase + wn + j * 8 + 2 * t;
#pragma unroll
            for (int half = 0; half < 2; half++) {
                int r = mBase + wm + i * 16 + g + half * 8;
                if (r >= Mr) continue;
                float v0 = acc[i][j][half * 2 + 0];
                float v1 = acc[i][j][half * 2 + 1];
                if (EPI == 0) {
                    v0 = softplusf(v0);
                    v1 = softplusf(v1);
                    __nv_bfloat162 H, L;
                    split2(v0, H.x, L.x);
                    split2(v1, H.y, L.y);
                    *reinterpret_cast<__nv_bfloat162*>(outHi + (long)r * ldS + c0) = H;
                    *reinterpret_cast<__nv_bfloat162*>(outLo + (long)r * ldS + c0) = L;
                } else {
                    if (c0 < NcValid) {
                        float2 rr = *reinterpret_cast<const float2*>(resid + (long)r * TT + c0);
                        v0 += rr.x + cvec[c0];
                        v1 += rr.y + cvec[c0 + 1];
                        float2 o; o.x = v0; o.y = v1;
                        *reinterpret_cast<float2*>(outF + (long)r * TT + c0) = o;
                        __nv_bfloat162 H, L;
                        split2(v0, H.x, L.x);
                        split2(v1, H.y, L.y);
                        *reinterpret_cast<__nv_bfloat162*>(outHi + (long)r * ldS + c0) = H;
                        *reinterpret_cast<__nv_bfloat162*>(outLo + (long)r * ldS + c0) = L;
                    }
                }
            }
        }
    }
}

// ---------------------------------------------------------------------------
// fc2: out(N,24) = X(N,168) @ Wfc2(24,168)^T.  Weight in smem, broadcast LDS.
// ---------------------------------------------------------------------------
__global__ void __launch_bounds__(128)
fc2_kernel(const float* __restrict__ X, const float* __restrict__ W,
           float* __restrict__ out, int N)
{
    __shared__ float sW[HORZ * TT];
    for (int i = threadIdx.x; i < HORZ * TT; i += 128) sW[i] = W[i];
    __syncthreads();
    int row = blockIdx.x * 128 + threadIdx.x;
    if (row >= N) return;
    float acc[HORZ];
#pragma unroll
    for (int j = 0; j < HORZ; j++) acc[j] = 0.f;
    const float4* xr = reinterpret_cast<const float4*>(X + (long)row * TT);
    for (int k4 = 0; k4 < TT / 4; k4++) {
        float4 xv = xr[k4];
#pragma unroll
        for (int j = 0; j < HORZ; j++) {
            const float4 wv = *reinterpret_cast<const float4*>(&sW[j * TT + k4 * 4]);
            acc[j] += xv.x * wv.x + xv.y * wv.y + xv.z * wv.z + xv.w * wv.w;
        }
    }
#pragma unroll
    for (int j = 0; j < HORZ; j++) out[(long)row * HORZ + j] = acc[j];
}

// ---------------------------------------------------------------------------
extern "C" void kernel_launch(void* const* d_in, const int* in_sizes, int n_in,
                              void* d_out, int out_size)
{
    const float* x    = (const float*)d_in[0];
    const float* Wl   = (const float*)d_in[1];
    const float* Wl1  = (const float*)d_in[2];
    const float* Wv   = (const float*)d_in[7];
    const float* bv   = (const float*)d_in[8];
    const float* Wo   = (const float*)d_in[9];
    const float* bo   = (const float*)d_in[10];
    const float* W20  = (const float*)d_in[11];
    const float* Wfc2 = (const float*)d_in[12];
    float* out = (float*)d_out;

    const int N = in_sizes[0] / TT;

    float *pX, *pTmp, *pM, *pC;
    cudaGetSymbolAddress((void**)&pX,   g_X);
    cudaGetSymbolAddress((void**)&pTmp, g_tmp);
    cudaGetSymbolAddress((void**)&pM,   g_M);
    cudaGetSymbolAddress((void**)&pC,   g_c);
    __nv_bfloat16 *pxs[2], *pXs[2], *pH1[2], *pH2[2], *pWls[2], *pWl1s[2], *pMs[2];
    cudaGetSymbolAddress((void**)&pxs[0],   g_xs);    pxs[1]   = pxs[0]   + (long)NSER * KP1;
    cudaGetSymbolAddress((void**)&pXs[0],   g_Xs);    pXs[1]   = pXs[0]   + (long)NSER * KP1;
    cudaGetSymbolAddress((void**)&pH1[0],   g_H1s);   pH1[1]   = pH1[0]   + (long)NSER * UU;
    cudaGetSymbolAddress((void**)&pH2[0],   g_H2s);   pH2[1]   = pH2[0]   + (long)NSER * UU;
    cudaGetSymbolAddress((void**)&pWls[0],  g_Wls);   pWls[1]  = pWls[0]  + (long)NBLK * UU * KP1;
    cudaGetSymbolAddress((void**)&pWl1s[0], g_Wl1s);  pWl1s[1] = pWl1s[0] + (long)NBLK * UU * UU;
    cudaGetSymbolAddress((void**)&pMs[0],   g_Ms);    pMs[1]   = pMs[0]   + (long)NBLK * UU * UU;

    // host-side, not a stream op: legal during capture, no static guards
    cudaFuncSetAttribute(mma_gemm<0>, cudaFuncAttributeMaxDynamicSharedMemorySize, SMEM_DYN);
    cudaFuncSetAttribute(mma_gemm<1>, cudaFuncAttributeMaxDynamicSharedMemorySize, SMEM_DYN);

    // ---- weight folding ----
    dim3 t16(16, 16);
    gemm_nn_batched<<<dim3(16, 16, NBLK), t16>>>(Wo, (long)UU * UU, Wv, (long)UU * UU,
                                                 pTmp, (long)UU * UU, UU, UU, UU);
    gemm_nn_batched<<<dim3(16, 11, NBLK), t16>>>(W20, (long)TT * UU, pTmp, (long)UU * UU,
                                                 pM, (long)TT * UU, TT, UU, UU);
    bias_fold<<<NBLK, UU>>>(Wo, bv, bo, W20);

    // ---- splits ----
    {
        long tot;
        tot = (long)NBLK * UU * KP1;   // Wl (768,168)->(768,192)
        split_pad<<<(int)((tot + 255) / 256), 256>>>(Wl, NBLK * UU, TT, pWls[0], pWls[1], tot, KP1);
        tot = (long)NBLK * UU * UU;    // Wl1 straight
        split_pad<<<(int)((tot + 255) / 256), 256>>>(Wl1, NBLK * UU, UU, pWl1s[0], pWl1s[1], tot, UU);
        for (int b = 0; b < NBLK; b++) { // M: (168,256)->(256,256) per block
            tot = (long)UU * UU;
            split_pad<<<(int)((tot + 255) / 256), 256>>>(pM + (long)b * TT * UU, TT, UU,
                pMs[0] + (long)b * UU * UU, pMs[1] + (long)b * UU * UU, tot, UU);
        }
        tot = (long)N * KP1;           // x (N,168)->(N,192)
        split_pad<<<(int)((tot + 255) / 256), 256>>>(x, N, TT, pxs[0], pxs[1], tot, KP1);
    }

    const int mt = (N + 127) / 128;
    for (int b = 0; b < NBLK; b++) {
        const __nv_bfloat16* Ah = (b == 0) ? pxs[0] : pXs[0];
        const __nv_bfloat16* Al = (b == 0) ? pxs[1] : pXs[1];
        // H1 = softplus(A @ Wl_b^T)
        mma_gemm<0><<<dim3(2, mt), 256, SMEM_DYN>>>(
            Ah, Al, pWls[0] + (long)b * UU * KP1, pWls[1] + (long)b * UU * KP1,
            N, KP1, UU, pH1[0], pH1[1], UU, nullptr, nullptr, nullptr);
        // H2 = softplus(H1 @ Wl1_b^T)
        mma_gemm<0><<<dim3(2, mt), 256, SMEM_DYN>>>(
            pH1[0], pH1[1], pWl1s[0] + (long)b * UU * UU, pWl1s[1] + (long)b * UU * UU,
            N, UU, UU, pH2[0], pH2[1], UU, nullptr, nullptr, nullptr);
        // X = resid + H2 @ M_b^T + c_b   (fp32 X + split for next block)
        mma_gemm<1><<<dim3(2, mt), 256, SMEM_DYN>>>(
            pH2[0], pH2[1], pMs[0] + (long)b * UU * UU, pMs[1] + (long)b * UU * UU,
            N, UU, TT, pXs[0], pXs[1], KP1, pX, (b == 0) ? x : pX, pC + (long)b * TT);
    }
    // out = X @ Wfc2^T
    fc2_kernel<<<mt, 128>>>(pX, Wfc2, out, N);
}

// round 10
// speedup vs baseline: 1.8251x; 1.1330x over previous
#include <cuda_runtime.h>
#include <cuda_bf16.h>
#include <math.h>

// ---------------------------------------------------------------------------
// Model_89197880803680.
// Attention collapses (all L tokens identical -> softmax uniform -> o == v).
// Per block:  x += softplus(softplus(x Wl^T) Wl1^T) M^T + c,
//   M = W20 Wo Wv,  c = W20 (Wo bv + bo).   Final: out = x Wfc2^T.
// GEMMs: mma.sync bf16 3-term split (hi*hi + hi*lo + lo*hi, f32 acc),
// fragments fed via ldmatrix.x4. (tcgen05 unavailable: harness PTX targets
// sm_103 without the 'a' suffix -> all tcgen05 features rejected by ptxas.)
// ---------------------------------------------------------------------------

#define NSER 19000
#define TT   168
#define UU   256
#define HORZ 24
#define NBLK 3
#define KP1  192          // padded K for 168

typedef unsigned int uint;

// fp32 scratch
__device__ float g_X  [NSER * TT];
__device__ float g_tmp[NBLK * UU * UU];
__device__ float g_M  [NBLK * TT * UU];
__device__ float g_c  [NBLK * TT];

// bf16 split buffers [0]=hi, [1]=lo
__device__ __nv_bfloat16 g_xs  [2][NSER * KP1];
__device__ __nv_bfloat16 g_Xs  [2][NSER * KP1];   // pad cols 168..191 stay 0
__device__ __nv_bfloat16 g_H1s [2][NSER * UU];
__device__ __nv_bfloat16 g_H2s [2][NSER * UU];
__device__ __nv_bfloat16 g_Wls [2][NBLK * UU * KP1];
__device__ __nv_bfloat16 g_Wl1s[2][NBLK * UU * UU];
__device__ __nv_bfloat16 g_Ms  [2][NBLK * UU * UU];  // M padded to 256 rows

__device__ __forceinline__ float softplusf(float v) {
    return v > 20.f ? v : log1pf(__expf(v));
}
__device__ __forceinline__ void split2(float v, __nv_bfloat16& h, __nv_bfloat16& l) {
    h = __float2bfloat16(v);
    l = __float2bfloat16(v - __bfloat162float(h));
}

// ---------------------------------------------------------------------------
// weight folding (tiny, fp32)
// ---------------------------------------------------------------------------
__global__ void gemm_nn_batched(const float* __restrict__ A, long sA,
                                const float* __restrict__ B, long sB,
                                float* __restrict__ C, long sC,
                                int Mr, int Nc, int K)
{
    __shared__ float As[16][16];
    __shared__ float Bs[16][17];
    int b = blockIdx.z;
    A += (long)b * sA; B += (long)b * sB; C += (long)b * sC;
    int row = blockIdx.y * 16 + threadIdx.y;
    int col = blockIdx.x * 16 + threadIdx.x;
    float acc = 0.f;
    for (int k0 = 0; k0 < K; k0 += 16) {
        As[threadIdx.y][threadIdx.x] = (row < Mr) ? A[(long)row * K + k0 + threadIdx.x] : 0.f;
        Bs[threadIdx.y][threadIdx.x] = (col < Nc) ? B[(long)(k0 + threadIdx.y) * Nc + col] : 0.f;
        __syncthreads();
#pragma unroll
        for (int k = 0; k < 16; k++) acc += As[threadIdx.y][k] * Bs[k][threadIdx.x];
        __syncthreads();
    }
    if (row < Mr && col < Nc) C[(long)row * Nc + col] = acc;
}

__global__ void bias_fold(const float* __restrict__ Wo, const float* __restrict__ bv,
                          const float* __restrict__ bo, const float* __restrict__ W20)
{
    int b = blockIdx.x, t = threadIdx.x;
    const float* Wo_b  = Wo  + (long)b * UU * UU;
    const float* W20_b = W20 + (long)b * TT * UU;
    __shared__ float sbvo[UU];
    float acc = bo[b * UU + t];
    for (int k = 0; k < UU; k++) acc += Wo_b[t * UU + k] * bv[b * UU + k];
    sbvo[t] = acc;
    __syncthreads();
    if (t < TT) {
        float a = 0.f;
        for (int i = 0; i < UU; i++) a += W20_b[t * UU + i] * sbvo[i];
        g_c[b * TT + t] = a;
    }
}

__global__ void split_pad(const float* __restrict__ src, int rows_in, int Kin,
                          __nv_bfloat16* __restrict__ hi, __nv_bfloat16* __restrict__ lo,
                          long total, int Kout)
{
    long idx = (long)blockIdx.x * blockDim.x + threadIdx.x;
    if (idx >= total) return;
    int r = (int)(idx / Kout), c = (int)(idx % Kout);
    float v = (r < rows_in && c < Kin) ? src[(long)r * Kin + c] : 0.f;
    __nv_bfloat16 h, l;
    split2(v, h, l);
    hi[idx] = h; lo[idx] = l;
}

// ---------------------------------------------------------------------------
// Tensor-core GEMM: C(m,n) = sum_k A[m,k]*B[n,k],  A/B as bf16 hi+lo splits.
// BM=BN=128, BK=32, 256 threads, 8 warps (2x4), warp tile 64x32.
// cp.async double buffered; fragments via ldmatrix.x4. K % 32 == 0.
// B buffers have >= nBase+128 rows (weights padded to 256).
// EPI 0: H = softplus(acc)           -> split store (ld 256)
// EPI 1: v = resid + acc + cvec[n]   -> fp32 X (ld 168) + split store (ld 192)
// ---------------------------------------------------------------------------
#define TILE_B 10240                    // bytes per 128x40-bf16 tile
#define STAGE_B (4 * TILE_B)            // Ahi,Alo,Bhi,Blo
#define SMEM_DYN (2 * STAGE_B)          // 81920

__device__ __forceinline__ void cpa16(uint dst, const void* src, bool pred) {
    int sz = pred ? 16 : 0;
    asm volatile("cp.async.cg.shared.global [%0], [%1], 16, %2;\n"
                 :: "r"(dst), "l"(src), "r"(sz));
}
__device__ __forceinline__ void mma16816(float* c, const uint* a, const uint* b) {
    asm volatile("mma.sync.aligned.m16n8k16.row.col.f32.bf16.bf16.f32 "
                 "{%0,%1,%2,%3}, {%4,%5,%6,%7}, {%8,%9}, {%0,%1,%2,%3};"
                 : "+f"(c[0]), "+f"(c[1]), "+f"(c[2]), "+f"(c[3])
                 : "r"(a[0]), "r"(a[1]), "r"(a[2]), "r"(a[3]), "r"(b[0]), "r"(b[1]));
}
__device__ __forceinline__ void ldsm4(uint& r0, uint& r1, uint& r2, uint& r3, uint addr) {
    asm volatile("ldmatrix.sync.aligned.m8n8.x4.shared.b16 {%0,%1,%2,%3}, [%4];"
                 : "=r"(r0), "=r"(r1), "=r"(r2), "=r"(r3) : "r"(addr));
}

template <int EPI>
__global__ void __launch_bounds__(256)
mma_gemm(const __nv_bfloat16* __restrict__ Ahi, const __nv_bfloat16* __restrict__ Alo,
         const __nv_bfloat16* __restrict__ Bhi, const __nv_bfloat16* __restrict__ Blo,
         int Mr, int K, int NcValid,
         __nv_bfloat16* __restrict__ outHi, __nv_bfloat16* __restrict__ outLo, int ldS,
         float* __restrict__ outF, const float* __restrict__ resid,
         const float* __restrict__ cvec)
{
    extern __shared__ __nv_bfloat16 sm[];
    const int tid   = threadIdx.x;
    const int mBase = blockIdx.y * 128;
    const int nBase = blockIdx.x * 128;
    const uint smBase = (uint)__cvta_generic_to_shared(sm);

    const int warp = tid >> 5, lane = tid & 31;
    const int g = lane >> 2, t = lane & 3;
    const int wm = (warp >> 2) * 64;   // 0 / 64
    const int wn = (warp & 3) * 32;    // 0..96

    // ldmatrix lane-address components: lane group q provides matrix q
    const int q  = lane >> 3;          // 0..3
    const int rr = lane & 7;           // row within 8
    const int lmRow = (q & 1) * 8 + rr;     // 0..15 (row within 16-row frag)
    const int lmKB  = (q >> 1) * 16;        // byte offset: 0 or 16 (8 bf16)

    float acc[4][4][4];
#pragma unroll
    for (int i = 0; i < 4; i++)
#pragma unroll
        for (int j = 0; j < 4; j++)
#pragma unroll
            for (int r = 0; r < 4; r++) acc[i][j][r] = 0.f;

    const int nIter = K >> 5;

    // loader: 512 int4 per tile-kind, 2 per thread
    const int lrow0 = tid >> 2;            // 0..63
    const int lq    = tid & 3;             // 16B chunk within 64B row chunk

    auto issue_stage = [&](int it, int s) {
        const long k0 = (long)it << 5;
        uint base = smBase + s * STAGE_B;
#pragma unroll
        for (int p = 0; p < 2; p++) {
            int row = lrow0 + p * 64;
            uint soff = (uint)(row * 80 + lq * 16);
            long aoff = (long)(mBase + row) * K + k0 + lq * 8;
            bool pa = (mBase + row) < Mr;
            long aoffc = pa ? aoff : 0;
            cpa16(base + 0 * TILE_B + soff, Ahi + aoffc, pa);
            cpa16(base + 1 * TILE_B + soff, Alo + aoffc, pa);
            long boff = (long)(nBase + row) * K + k0 + lq * 8;
            cpa16(base + 2 * TILE_B + soff, Bhi + boff, true);
            cpa16(base + 3 * TILE_B + soff, Blo + boff, true);
        }
        asm volatile("cp.async.commit_group;");
    };

    issue_stage(0, 0);

    for (int it = 0; it < nIter; it++) {
        const int s = it & 1;
        if (it + 1 < nIter) {
            issue_stage(it + 1, s ^ 1);
            asm volatile("cp.async.wait_group 1;");
        } else {
            asm volatile("cp.async.wait_group 0;");
        }
        __syncthreads();

        const uint base = smBase + s * STAGE_B;
        const uint uAh = base, uAl = base + TILE_B;
        const uint uBh = base + 2 * TILE_B, uBl = base + 3 * TILE_B;

#pragma unroll
        for (int kh = 0; kh < 2; kh++) {
            const uint koff = (uint)(kh * 32 + lmKB);   // bytes within 80B row
            // B fragments: two ldmatrix.x4 per plane cover n 0..31 of warp tile
            uint bh0[4], bh1[4], bl0[4], bl1[4];
            {
                uint off0 = (uint)((wn + lmRow) * 80) + koff;
                uint off1 = (uint)((wn + 16 + lmRow) * 80) + koff;
                ldsm4(bh0[0], bh0[1], bh0[2], bh0[3], uBh + off0);
                ldsm4(bh1[0], bh1[1], bh1[2], bh1[3], uBh + off1);
                ldsm4(bl0[0], bl0[1], bl0[2], bl0[3], uBl + off0);
                ldsm4(bl1[0], bl1[1], bl1[2], bl1[3], uBl + off1);
            }
#pragma unroll
            for (int i = 0; i < 4; i++) {
                uint offA = (uint)((wm + i * 16 + lmRow) * 80) + koff;
                uint ah[4], al[4];
                ldsm4(ah[0], ah[1], ah[2], ah[3], uAh + offA);
                ldsm4(al[0], al[1], al[2], al[3], uAl + offA);
#pragma unroll
                for (int j = 0; j < 4; j++) {
                    const uint* bhG = (j < 2) ? bh0 : bh1;
                    const uint* blG = (j < 2) ? bl0 : bl1;
                    const int s2 = j & 1;
                    uint bh[2] = { bhG[s2], bhG[s2 + 2] };
                    uint bl[2] = { blG[s2], blG[s2 + 2] };
                    mma16816(acc[i][j], ah, bh);
                    mma16816(acc[i][j], ah, bl);
                    mma16816(acc[i][j], al, bh);
                }
            }
        }
        __syncthreads();
    }

    // epilogue (same thread<->element mapping as scalar version)
#pragma unroll
    for (int i = 0; i < 4; i++) {
#pragma unroll
        for (int j = 0; j < 4; j++) {
            int c0 = nBase + wn + j * 8 + 2 * t;
#pragma unroll
            for (int half = 0; half < 2; half++) {
                int r = mBase + wm + i * 16 + g + half * 8;
                if (r >= Mr) continue;
                float v0 = acc[i][j][half * 2 + 0];
                float v1 = acc[i][j][half * 2 + 1];
                if (EPI == 0) {
                    v0 = softplusf(v0);
                    v1 = softplusf(v1);
                    __nv_bfloat162 H, L;
                    split2(v0, H.x, L.x);
                    split2(v1, H.y, L.y);
                    *reinterpret_cast<__nv_bfloat162*>(outHi + (long)r * ldS + c0) = H;
                    *reinterpret_cast<__nv_bfloat162*>(outLo + (long)r * ldS + c0) = L;
                } else {
                    if (c0 < NcValid) {
                        float2 rv = *reinterpret_cast<const float2*>(resid + (long)r * TT + c0);
                        v0 += rv.x + cvec[c0];
                        v1 += rv.y + cvec[c0 + 1];
                        float2 o; o.x = v0; o.y = v1;
                        *reinterpret_cast<float2*>(outF + (long)r * TT + c0) = o;
                        __nv_bfloat162 H, L;
                        split2(v0, H.x, L.x);
                        split2(v1, H.y, L.y);
                        *reinterpret_cast<__nv_bfloat162*>(outHi + (long)r * ldS + c0) = H;
                        *reinterpret_cast<__nv_bfloat162*>(outLo + (long)r * ldS + c0) = L;
                    }
                }
            }
        }
    }
}

// ---------------------------------------------------------------------------
// fc2: out(N,24) = X(N,168) @ Wfc2(24,168)^T.  Weight in smem, broadcast LDS.
// ---------------------------------------------------------------------------
__global__ void __launch_bounds__(128)
fc2_kernel(const float* __restrict__ X, const float* __restrict__ W,
           float* __restrict__ out, int N)
{
    __shared__ float sW[HORZ * TT];
    for (int i = threadIdx.x; i < HORZ * TT; i += 128) sW[i] = W[i];
    __syncthreads();
    int row = blockIdx.x * 128 + threadIdx.x;
    if (row >= N) return;
    float acc[HORZ];
#pragma unroll
    for (int j = 0; j < HORZ; j++) acc[j] = 0.f;
    const float4* xr = reinterpret_cast<const float4*>(X + (long)row * TT);
    for (int k4 = 0; k4 < TT / 4; k4++) {
        float4 xv = xr[k4];
#pragma unroll
        for (int j = 0; j < HORZ; j++) {
            const float4 wv = *reinterpret_cast<const float4*>(&sW[j * TT + k4 * 4]);
            acc[j] += xv.x * wv.x + xv.y * wv.y + xv.z * wv.z + xv.w * wv.w;
        }
    }
#pragma unroll
    for (int j = 0; j < HORZ; j++) out[(long)row * HORZ + j] = acc[j];
}

// ---------------------------------------------------------------------------
extern "C" void kernel_launch(void* const* d_in, const int* in_sizes, int n_in,
                              void* d_out, int out_size)
{
    const float* x    = (const float*)d_in[0];
    const float* Wl   = (const float*)d_in[1];
    const float* Wl1  = (const float*)d_in[2];
    const float* Wv   = (const float*)d_in[7];
    const float* bv   = (const float*)d_in[8];
    const float* Wo   = (const float*)d_in[9];
    const float* bo   = (const float*)d_in[10];
    const float* W20  = (const float*)d_in[11];
    const float* Wfc2 = (const float*)d_in[12];
    float* out = (float*)d_out;

    const int N = in_sizes[0] / TT;

    float *pX, *pTmp, *pM, *pC;
    cudaGetSymbolAddress((void**)&pX,   g_X);
    cudaGetSymbolAddress((void**)&pTmp, g_tmp);
    cudaGetSymbolAddress((void**)&pM,   g_M);
    cudaGetSymbolAddress((void**)&pC,   g_c);
    __nv_bfloat16 *pxs[2], *pXs[2], *pH1[2], *pH2[2], *pWls[2], *pWl1s[2], *pMs[2];
    cudaGetSymbolAddress((void**)&pxs[0],   g_xs);    pxs[1]   = pxs[0]   + (long)NSER * KP1;
    cudaGetSymbolAddress((void**)&pXs[0],   g_Xs);    pXs[1]   = pXs[0]   + (long)NSER * KP1;
    cudaGetSymbolAddress((void**)&pH1[0],   g_H1s);   pH1[1]   = pH1[0]   + (long)NSER * UU;
    cudaGetSymbolAddress((void**)&pH2[0],   g_H2s);   pH2[1]   = pH2[0]   + (long)NSER * UU;
    cudaGetSymbolAddress((void**)&pWls[0],  g_Wls);   pWls[1]  = pWls[0]  + (long)NBLK * UU * KP1;
    cudaGetSymbolAddress((void**)&pWl1s[0], g_Wl1s);  pWl1s[1] = pWl1s[0] + (long)NBLK * UU * UU;
    cudaGetSymbolAddress((void**)&pMs[0],   g_Ms);    pMs[1]   = pMs[0]   + (long)NBLK * UU * UU;

    cudaFuncSetAttribute(mma_gemm<0>, cudaFuncAttributeMaxDynamicSharedMemorySize, SMEM_DYN);
    cudaFuncSetAttribute(mma_gemm<1>, cudaFuncAttributeMaxDynamicSharedMemorySize, SMEM_DYN);

    const int mt = (N + 127) / 128;
    long tot;

    // Launch order arranged so the 6th launch (ncu -s 5 -c 1) is a big GEMM.
    // 0: split Wl   1: split x   2: split Wl1
    tot = (long)NBLK * UU * KP1;
    split_pad<<<(int)((tot + 255) / 256), 256>>>(Wl, NBLK * UU, TT, pWls[0], pWls[1], tot, KP1);
    tot = (long)N * KP1;
    split_pad<<<(int)((tot + 255) / 256), 256>>>(x, N, TT, pxs[0], pxs[1], tot, KP1);
    tot = (long)NBLK * UU * UU;
    split_pad<<<(int)((tot + 255) / 256), 256>>>(Wl1, NBLK * UU, UU, pWl1s[0], pWl1s[1], tot, UU);

    // 3,4: weight folding GEMMs
    dim3 t16(16, 16);
    gemm_nn_batched<<<dim3(16, 16, NBLK), t16>>>(Wo, (long)UU * UU, Wv, (long)UU * UU,
                                                 pTmp, (long)UU * UU, UU, UU, UU);
    gemm_nn_batched<<<dim3(16, 11, NBLK), t16>>>(W20, (long)TT * UU, pTmp, (long)UU * UU,
                                                 pM, (long)TT * UU, TT, UU, UU);

    // 5: GEMM1 block 0  <- ncu captures this launch
    mma_gemm<0><<<dim3(2, mt), 256, SMEM_DYN>>>(
        pxs[0], pxs[1], pWls[0], pWls[1],
        N, KP1, UU, pH1[0], pH1[1], UU, nullptr, nullptr, nullptr);

    // 6: bias fold, 7-9: M splits
    bias_fold<<<NBLK, UU>>>(Wo, bv, bo, W20);
    for (int b = 0; b < NBLK; b++) {
        tot = (long)UU * UU;
        split_pad<<<(int)((tot + 255) / 256), 256>>>(pM + (long)b * TT * UU, TT, UU,
            pMs[0] + (long)b * UU * UU, pMs[1] + (long)b * UU * UU, tot, UU);
    }

    for (int b = 0; b < NBLK; b++) {
        if (b > 0) {
            // H1 = softplus(X @ Wl_b^T)   K=192
            mma_gemm<0><<<dim3(2, mt), 256, SMEM_DYN>>>(
                pXs[0], pXs[1], pWls[0] + (long)b * UU * KP1, pWls[1] + (long)b * UU * KP1,
                N, KP1, UU, pH1[0], pH1[1], UU, nullptr, nullptr, nullptr);
        }
        // H2 = softplus(H1 @ Wl1_b^T)  K=256
        mma_gemm<0><<<dim3(2, mt), 256, SMEM_DYN>>>(
            pH1[0], pH1[1], pWl1s[0] + (long)b * UU * UU, pWl1s[1] + (long)b * UU * UU,
            N, UU, UU, pH2[0], pH2[1], UU, nullptr, nullptr, nullptr);
        // X = resid + H2 @ M_b^T + c_b   (fp32 X + split for next block)
        mma_gemm<1><<<dim3(2, mt), 256, SMEM_DYN>>>(
            pH2[0], pH2[1], pMs[0] + (long)b * UU * UU, pMs[1] + (long)b * UU * UU,
            N, UU, TT, pXs[0], pXs[1], KP1, pX, (b == 0) ? x : pX, pC + (long)b * TT);
    }
    // out = X @ Wfc2^T
    fc2_kernel<<<mt, 128>>>(pX, Wfc2, out, N);
}